// round 7
// baseline (speedup 1.0000x reference)
#include <cuda_runtime.h>
#include <cstdint>

// FP4Quantizer — single persistent kernel (one graph node):
//   phase1: per-64-block scale via exact 5-REDUX/4-ballot top-5 selection
//           (clear exactly one instance per round); all lanes see uniform
//           w4/w5 -> quantize own elems to int8 codes (4*level*sign);
//           per-CTA scale min/max partials.
//   sync  : fence-counter last-CTA reduction publishes (smin, ss, rss) to
//           g_gmm, bumps epoch g_done; all CTAs spin on epoch.
//   phase2: decode codes (PRMT sign-extend + I2F + FMUL) -> out.
//
// Co-residency: grid 512 <= 148 SMs * 4 CTAs/SM forced by launch_bounds.

#define QBLK 64
#define MAX_QBLOCKS (262144 + 8192)
#define GRID 512
#define TPB  256

__device__ float    g_scales[MAX_QBLOCKS];
__device__ uint4    g_codes4[MAX_QBLOCKS * 4];   // 64 int8 codes per block
__device__ unsigned g_pmin[GRID];
__device__ unsigned g_pmax[GRID];
__device__ unsigned g_ctr  = 0;                  // wraps to 0 every launch
__device__ unsigned g_done = 0;                  // epoch, monotone
__device__ float4   g_gmm;                       // (smin, ss, rss, -)

__device__ __forceinline__ unsigned absbits(float f) {
    return __float_as_uint(f) & 0x7FFFFFFFu;
}

// quantize one value -> int code = 4*level*sign in {0,±3,±4,±6,±8,±12}
// (levels {0,.75,1,1.5,2,3}): round |x/s| to 1 mantissa bit, clamp [0.75,3]
// in u32 domain, zero at/below 0.375, map exponent-bits -> 4*level via LUT.
__device__ __forceinline__ int qc(float val, float inv) {
    float xs = val * inv;
    unsigned ub = __float_as_uint(xs);
    unsigned uu = ub & 0x7FFFFFFFu;
    unsigned t  = (uu + 0x00200000u) & 0xFFC00000u;
    t = t < 0x40400000u ? t : 0x40400000u;
    t = t > 0x3F400000u ? t : 0x3F400000u;
    // t>>20 in {0x3F4,0x3F8,0x3FC,0x400,0x404} -> {3,4,6,8,12}
    int lvl4 = (int)((0xC8643u >> ((t >> 20) - 0x3F4u)) & 0xFu);
    lvl4 = (uu > 0x3EC00000u) ? lvl4 : 0;
    return (ub & 0x80000000u) ? -lvl4 : lvl4;
}

// decode: sign-extend byte (PRMT), int->float, scale by deq/4
__device__ __forceinline__ float dec8(unsigned wv, unsigned sel, float dqq) {
    int t;
    asm("prmt.b32 %0, %1, %1, %2;" : "=r"(t) : "r"(wv), "r"(sel));
    return (float)t * dqq;
}

// generic-path quantize-dequantize (fallback only)
__device__ __forceinline__ float qdq_one(float xv, float inv, float deq) {
    float xs = xv * inv;
    unsigned ub = __float_as_uint(xs);
    unsigned uu = ub & 0x7FFFFFFFu;
    unsigned t  = (uu + 0x00200000u) & 0xFFC00000u;
    t = t < 0x40400000u ? t : 0x40400000u;
    t = t > 0x3F400000u ? t : 0x3F400000u;
    float lvl = (uu > 0x3EC00000u) ? __uint_as_float(t) : 0.0f;
    float o = lvl * deq;
    return __uint_as_float(__float_as_uint(o) | (ub & 0x80000000u));
}

__global__ void __launch_bounds__(TPB, 4)
fused_kernel(const float* __restrict__ x, float* __restrict__ out,
             int n, int fast)
{
    __shared__ unsigned s_rmin[8], s_rmax[8];
    __shared__ unsigned s_snap;
    __shared__ int s_last;

    const int tid   = threadIdx.x;
    const int lane  = tid & 31;
    const int w     = tid >> 5;
    const int gwarp = (blockIdx.x * TPB + tid) >> 5;
    const int nwarps = (GRID * TPB) >> 5;
    const int gtid  = blockIdx.x * TPB + tid;
    const int NT    = GRID * TPB;

    // epoch snapshot BEFORE this CTA's counter arrive (so the publisher's
    // bump — which causally follows our arrive — cannot be in the snapshot)
    if (tid == 0) s_snap = __ldcg(&g_done);
    __syncthreads();

    unsigned mymin = 0xFFFFFFFFu, mymax = 0u;

    // ------------------------- phase 1 -------------------------
    if (fast) {                                  // n % 128 == 0
        const int npairs = n >> 7;
        short* codes16 = reinterpret_cast<short*>(g_codes4);
        for (int p = gwarp; p < npairs; p += nwarps) {
            long base = (long)p * 128 + lane * 2;
            float2 u = *reinterpret_cast<const float2*>(x + base);
            float2 v = *reinterpret_cast<const float2*>(x + base + QBLK);
            unsigned a0 = absbits(u.x), a1 = absbits(u.y);
            unsigned c0 = absbits(v.x), c1 = absbits(v.y);

            // exact top-5: 5 REDUX rounds, clear exactly ONE instance/round
            unsigned b0 = a0, b1 = a1, e0 = c0, e1 = c1;
            unsigned w4a = 0u, w5a = 0u, w4b = 0u, w5b = 0u;
            #pragma unroll
            for (int r = 0; r < 5; ++r) {
                unsigned ma = max(b0, b1), mb = max(e0, e1);
                unsigned wa = __reduce_max_sync(0xFFFFFFFFu, ma);
                unsigned wb = __reduce_max_sync(0xFFFFFFFFu, mb);
                if (r == 3) { w4a = wa; w4b = wb; }
                if (r == 4) { w5a = wa; w5b = wb; }
                else {
                    unsigned bala = __ballot_sync(0xFFFFFFFFu, ma == wa);
                    unsigned balb = __ballot_sync(0xFFFFFFFFu, mb == wb);
                    if (lane == __ffs((int)bala) - 1) { if (b0 == wa) b0 = 0u; else b1 = 0u; }
                    if (lane == __ffs((int)balb) - 1) { if (e0 == wb) e0 = 0u; else e1 = 0u; }
                }
            }
            // REDUX results are warp-uniform: every lane knows the scales
            float q4a = __uint_as_float(w4a), q5a = __uint_as_float(w5a);
            float q4b = __uint_as_float(w4b), q5b = __uint_as_float(w5b);
            float sA = fmaxf(fmaf(0.85f, q4a - q5a, q5a), 1e-8f);
            float sB = fmaxf(fmaf(0.85f, q4b - q5b, q5b), 1e-8f);
            float invA = 1.0f / sA, invB = 1.0f / sB;

            int cA0 = qc(u.x, invA), cA1 = qc(u.y, invA);
            int cB0 = qc(v.x, invB), cB1 = qc(v.y, invB);
            codes16[(2 * p)     * 32 + lane] = (short)((cA0 & 0xFF) | ((cA1 & 0xFF) << 8));
            codes16[(2 * p + 1) * 32 + lane] = (short)((cB0 & 0xFF) | ((cB1 & 0xFF) << 8));

            if (lane == 0) {
                g_scales[2 * p]     = sA;
                g_scales[2 * p + 1] = sB;
                unsigned sa = __float_as_uint(sA), sb = __float_as_uint(sB);
                unsigned lo = sa < sb ? sa : sb;
                unsigned hi = sa > sb ? sa : sb;
                mymin = mymin < lo ? mymin : lo;
                mymax = mymax > hi ? mymax : hi;
            }
        }
    } else {                                     // generic fallback: scales only
        const int nblocks = (n + QBLK - 1) / QBLK;
        for (int b = gwarp; b < nblocks; b += nwarps) {
            long base = (long)b * QBLK + lane * 2;
            float x0 = 0.0f, x1 = 0.0f;
            if (base + 1 < (long)n) {
                float2 t = *reinterpret_cast<const float2*>(x + base);
                x0 = t.x; x1 = t.y;
            } else if (base < (long)n) {
                x0 = x[base];
            }
            unsigned b0 = absbits(x0), b1 = absbits(x1);
            unsigned w4 = 0u, w5 = 0u;
            #pragma unroll
            for (int r = 0; r < 5; ++r) {
                unsigned m  = max(b0, b1);
                unsigned ww = __reduce_max_sync(0xFFFFFFFFu, m);
                if (r == 3) w4 = ww;
                if (r == 4) w5 = ww;
                else {
                    unsigned bal = __ballot_sync(0xFFFFFFFFu, m == ww);
                    if (lane == __ffs((int)bal) - 1) { if (b0 == ww) b0 = 0u; else b1 = 0u; }
                }
            }
            if (lane == 0) {
                float s = fmaxf(fmaf(0.85f, __uint_as_float(w4) - __uint_as_float(w5),
                                     __uint_as_float(w5)), 1e-8f);
                g_scales[b] = s;
                unsigned sb = __float_as_uint(s);
                mymin = mymin < sb ? mymin : sb;
                mymax = mymax > sb ? mymax : sb;
            }
        }
    }

    // --------------- grid sync: publish (smin, ss, rss) ---------------
    mymin = __reduce_min_sync(0xFFFFFFFFu, mymin);
    mymax = __reduce_max_sync(0xFFFFFFFFu, mymax);
    if (lane == 0) { s_rmin[w] = mymin; s_rmax[w] = mymax; }
    __syncthreads();
    if (tid == 0) {
        unsigned a = 0xFFFFFFFFu, b = 0u;
        #pragma unroll
        for (int i = 0; i < TPB / 32; ++i) {
            a = a < s_rmin[i] ? a : s_rmin[i];
            b = b > s_rmax[i] ? b : s_rmax[i];
        }
        g_pmin[blockIdx.x] = a;
        g_pmax[blockIdx.x] = b;
        __threadfence();
        unsigned old = atomicInc(&g_ctr, GRID - 1);   // wraps to 0 each launch
        s_last = (old == GRID - 1);
    }
    __syncthreads();
    if (s_last) {
        unsigned lmin = 0xFFFFFFFFu, lmax = 0u;
        for (int i = tid; i < GRID; i += TPB) {
            unsigned a = __ldcg(&g_pmin[i]);
            unsigned b = __ldcg(&g_pmax[i]);
            lmin = lmin < a ? lmin : a;
            lmax = lmax > b ? lmax : b;
        }
        lmin = __reduce_min_sync(0xFFFFFFFFu, lmin);
        lmax = __reduce_max_sync(0xFFFFFFFFu, lmax);
        if (lane == 0) { s_rmin[w] = lmin; s_rmax[w] = lmax; }
        __syncthreads();
        if (tid == 0) {
            unsigned a = 0xFFFFFFFFu, b = 0u;
            #pragma unroll
            for (int i = 0; i < TPB / 32; ++i) {
                a = a < s_rmin[i] ? a : s_rmin[i];
                b = b > s_rmax[i] ? b : s_rmax[i];
            }
            float smin = __uint_as_float(a);
            float smax = __uint_as_float(b);
            bool  cond = smax > smin;
            float dd   = smax - smin;
            float ssc  = cond ? dd * (1.0f / 255.0f) : 1.0f;
            float rss  = cond ? 255.0f / dd : 0.0f;
            g_gmm = make_float4(smin, ssc, rss, 0.0f);
            __threadfence();
            atomicAdd(&g_done, 1u);                   // bump epoch
        }
    }
    // spin on epoch (includes the last CTA: it sees its own bump)
    if (tid == 0) {
        while (__ldcg(&g_done) == s_snap) __nanosleep(64);
    }
    __syncthreads();

    // ------------------------- phase 2 -------------------------
    float4 gmm = __ldcg(&g_gmm);
    const float smin = gmm.x, ssc = gmm.y, rss = gmm.z;

    if (fast) {
        float4* __restrict__ o4 = reinterpret_cast<float4*>(out);
        const int nchunks = n >> 4;                  // 16 elems per chunk
        for (int c = gtid; c < nchunks; c += NT) {
            uint4 wv = g_codes4[c];
            float s  = g_scales[c >> 2];
            float q  = rintf((s - smin) * rss);
            q = fminf(fmaxf(q, 0.0f), 255.0f);
            float dqq = q * ssc * 0.25f;             // deq / 4 (codes are 4*level)
            float4 r0, r1, r2, r3;
            r0.x = dec8(wv.x, 0x8880u, dqq); r0.y = dec8(wv.x, 0x9991u, dqq);
            r0.z = dec8(wv.x, 0xAAA2u, dqq); r0.w = dec8(wv.x, 0xBBB3u, dqq);
            r1.x = dec8(wv.y, 0x8880u, dqq); r1.y = dec8(wv.y, 0x9991u, dqq);
            r1.z = dec8(wv.y, 0xAAA2u, dqq); r1.w = dec8(wv.y, 0xBBB3u, dqq);
            r2.x = dec8(wv.z, 0x8880u, dqq); r2.y = dec8(wv.z, 0x9991u, dqq);
            r2.z = dec8(wv.z, 0xAAA2u, dqq); r2.w = dec8(wv.z, 0xBBB3u, dqq);
            r3.x = dec8(wv.w, 0x8880u, dqq); r3.y = dec8(wv.w, 0x9991u, dqq);
            r3.z = dec8(wv.w, 0xAAA2u, dqq); r3.w = dec8(wv.w, 0xBBB3u, dqq);
            __stcs(o4 + c * 4 + 0, r0);
            __stcs(o4 + c * 4 + 1, r1);
            __stcs(o4 + c * 4 + 2, r2);
            __stcs(o4 + c * 4 + 3, r3);
        }
    } else {
        for (int i = gtid; i < n; i += NT) {
            float s = g_scales[i >> 6];
            float q = rintf((s - smin) * rss);
            q = fminf(fmaxf(q, 0.0f), 255.0f);
            float deq = q * ssc;
            out[i] = qdq_one(x[i], 1.0f / s, deq);
        }
    }
}

extern "C" void kernel_launch(void* const* d_in, const int* in_sizes, int n_in,
                              void* d_out, int out_size) {
    const float* x = (const float*)d_in[0];
    float* out = (float*)d_out;
    int n = in_sizes[0];
    int fast = ((n & 127) == 0) && ((n >> 6) <= MAX_QBLOCKS);

    fused_kernel<<<GRID, TPB>>>(x, out, n, fast);
}

// round 8
// speedup vs baseline: 1.2401x; 1.2401x over previous
#include <cuda_runtime.h>
#include <cstdint>

// FP4Quantizer, 2-node pipeline (no init kernel):
//   pass1 (grid 4096x256): per-64-block scale via exact 5-REDUX/4-ballot
//          top-5 selection, ILP-2 over block pairs; REDUX results are
//          warp-uniform -> each lane quantizes its own 4 elems to int8
//          codes (4*level*sign); fence-counter last-CTA publishes
//          (smin, ss, rss) to g_gmm.
//   pass2 (grid 4096x256): decode codes (PRMT sign-extend + I2F + FMUL),
//          reads 9MB (L2-hot) + writes 64MB. Never re-reads x.

#define QBLK 64
#define MAX_QBLOCKS (262144 + 8192)
#define GRID1 4096
#define TPB   256

__device__ float    g_scales[MAX_QBLOCKS];
__device__ uint4    g_codes4[MAX_QBLOCKS * 4];   // 64 int8 codes per block
__device__ unsigned g_pmin[GRID1];
__device__ unsigned g_pmax[GRID1];
__device__ unsigned g_ctr = 0;                   // wraps to 0 every launch
__device__ float4   g_gmm;                       // (smin, ss, rss, -)

__device__ __forceinline__ unsigned absbits(float f) {
    return __float_as_uint(f) & 0x7FFFFFFFu;
}

// quantize one value -> int code = 4*level*sign in {0,±3,±4,±6,±8,±12}
// (levels {0,.75,1,1.5,2,3}): round |x/s| to 1 mantissa bit, clamp [0.75,3]
// in u32 domain, zero at/below 0.375 (argmin tie-to-lower), LUT exponent->4*level.
__device__ __forceinline__ int qc(float val, float inv) {
    float xs = val * inv;
    unsigned ub = __float_as_uint(xs);
    unsigned uu = ub & 0x7FFFFFFFu;
    unsigned t  = (uu + 0x00200000u) & 0xFFC00000u;
    t = t < 0x40400000u ? t : 0x40400000u;
    t = t > 0x3F400000u ? t : 0x3F400000u;
    // t>>20 in {0x3F4,0x3F8,0x3FC,0x400,0x404} -> {3,4,6,8,12}
    int lvl4 = (int)((0xC8643u >> ((t >> 20) - 0x3F4u)) & 0xFu);
    lvl4 = (uu > 0x3EC00000u) ? lvl4 : 0;
    return (ub & 0x80000000u) ? -lvl4 : lvl4;
}

// decode: sign-extend byte (PRMT), int->float, scale by deq/4
__device__ __forceinline__ float dec8(unsigned wv, unsigned sel, float dqq) {
    int t;
    asm("prmt.b32 %0, %1, %1, %2;" : "=r"(t) : "r"(wv), "r"(sel));
    return (float)t * dqq;
}

// generic-path quantize-dequantize (fallback only)
__device__ __forceinline__ float qdq_one(float xv, float inv, float deq) {
    float xs = xv * inv;
    unsigned ub = __float_as_uint(xs);
    unsigned uu = ub & 0x7FFFFFFFu;
    unsigned t  = (uu + 0x00200000u) & 0xFFC00000u;
    t = t < 0x40400000u ? t : 0x40400000u;
    t = t > 0x3F400000u ? t : 0x3F400000u;
    float lvl = (uu > 0x3EC00000u) ? __uint_as_float(t) : 0.0f;
    float o = lvl * deq;
    return __uint_as_float(__float_as_uint(o) | (ub & 0x80000000u));
}

// CTA partial -> global publish -> last CTA computes (smin, ss, rss).
__device__ __forceinline__ void reduce_and_publish(unsigned mymin, unsigned mymax,
                                                   int tid, int lane, int w) {
    __shared__ unsigned s_rmin[TPB / 32], s_rmax[TPB / 32];
    __shared__ int s_last;
    mymin = __reduce_min_sync(0xFFFFFFFFu, mymin);
    mymax = __reduce_max_sync(0xFFFFFFFFu, mymax);
    if (lane == 0) { s_rmin[w] = mymin; s_rmax[w] = mymax; }
    __syncthreads();
    if (tid == 0) {
        unsigned a = 0xFFFFFFFFu, b = 0u;
        #pragma unroll
        for (int i = 0; i < TPB / 32; ++i) {
            a = a < s_rmin[i] ? a : s_rmin[i];
            b = b > s_rmax[i] ? b : s_rmax[i];
        }
        g_pmin[blockIdx.x] = a;
        g_pmax[blockIdx.x] = b;
        __threadfence();
        unsigned old = atomicInc(&g_ctr, gridDim.x - 1);  // wraps to 0 each launch
        s_last = (old == gridDim.x - 1);
    }
    __syncthreads();
    if (s_last) {
        unsigned lmin = 0xFFFFFFFFu, lmax = 0u;
        for (int i = tid; i < (int)gridDim.x; i += TPB) {
            unsigned a = __ldcg(&g_pmin[i]);
            unsigned b = __ldcg(&g_pmax[i]);
            lmin = lmin < a ? lmin : a;
            lmax = lmax > b ? lmax : b;
        }
        lmin = __reduce_min_sync(0xFFFFFFFFu, lmin);
        lmax = __reduce_max_sync(0xFFFFFFFFu, lmax);
        if (lane == 0) { s_rmin[w] = lmin; s_rmax[w] = lmax; }
        __syncthreads();
        if (tid == 0) {
            unsigned a = 0xFFFFFFFFu, b = 0u;
            #pragma unroll
            for (int i = 0; i < TPB / 32; ++i) {
                a = a < s_rmin[i] ? a : s_rmin[i];
                b = b > s_rmax[i] ? b : s_rmax[i];
            }
            float smin = __uint_as_float(a);
            float smax = __uint_as_float(b);
            bool  cond = smax > smin;
            float dd   = smax - smin;
            float ssc  = cond ? dd * (1.0f / 255.0f) : 1.0f;
            float rss  = cond ? 255.0f / dd : 0.0f;
            g_gmm = make_float4(smin, ssc, rss, 0.0f);
        }
    }
}

// ---------------- Pass 1 fast (n % 128 == 0) ----------------
__global__ void __launch_bounds__(TPB)
pass1_fast(const float* __restrict__ x, int npairs) {
    const int tid  = threadIdx.x;
    const int lane = tid & 31;
    const int w    = tid >> 5;
    const int warp = (blockIdx.x * TPB + tid) >> 5;
    const int nw   = (gridDim.x * TPB) >> 5;
    unsigned mymin = 0xFFFFFFFFu, mymax = 0u;
    short* codes16 = reinterpret_cast<short*>(g_codes4);

    for (int p = warp; p < npairs; p += nw) {
        long base = (long)p * 128 + lane * 2;
        float2 u = *reinterpret_cast<const float2*>(x + base);
        float2 v = *reinterpret_cast<const float2*>(x + base + QBLK);
        unsigned a0 = absbits(u.x), a1 = absbits(u.y);
        unsigned c0 = absbits(v.x), c1 = absbits(v.y);

        // exact top-5: 5 REDUX rounds, clear exactly ONE instance per round
        unsigned b0 = a0, b1 = a1, e0 = c0, e1 = c1;
        unsigned w4a = 0u, w5a = 0u, w4b = 0u, w5b = 0u;
        #pragma unroll
        for (int r = 0; r < 5; ++r) {
            unsigned ma = max(b0, b1), mb = max(e0, e1);
            unsigned wa = __reduce_max_sync(0xFFFFFFFFu, ma);
            unsigned wb = __reduce_max_sync(0xFFFFFFFFu, mb);
            if (r == 3) { w4a = wa; w4b = wb; }
            if (r == 4) { w5a = wa; w5b = wb; }
            else {
                unsigned bala = __ballot_sync(0xFFFFFFFFu, ma == wa);
                unsigned balb = __ballot_sync(0xFFFFFFFFu, mb == wb);
                if (lane == __ffs((int)bala) - 1) { if (b0 == wa) b0 = 0u; else b1 = 0u; }
                if (lane == __ffs((int)balb) - 1) { if (e0 == wb) e0 = 0u; else e1 = 0u; }
            }
        }
        // warp-uniform scales: every lane computes them, no broadcast needed
        float q4a = __uint_as_float(w4a), q5a = __uint_as_float(w5a);
        float q4b = __uint_as_float(w4b), q5b = __uint_as_float(w5b);
        float sA = fmaxf(fmaf(0.85f, q4a - q5a, q5a), 1e-8f);
        float sB = fmaxf(fmaf(0.85f, q4b - q5b, q5b), 1e-8f);
        float invA = 1.0f / sA, invB = 1.0f / sB;

        int cA0 = qc(u.x, invA), cA1 = qc(u.y, invA);
        int cB0 = qc(v.x, invB), cB1 = qc(v.y, invB);
        codes16[(2 * p)     * 32 + lane] = (short)((cA0 & 0xFF) | ((cA1 & 0xFF) << 8));
        codes16[(2 * p + 1) * 32 + lane] = (short)((cB0 & 0xFF) | ((cB1 & 0xFF) << 8));

        if (lane == 0) {
            g_scales[2 * p]     = sA;
            g_scales[2 * p + 1] = sB;
            unsigned sa = __float_as_uint(sA), sb = __float_as_uint(sB);
            unsigned lo = sa < sb ? sa : sb;
            unsigned hi = sa > sb ? sa : sb;
            mymin = mymin < lo ? mymin : lo;
            mymax = mymax > hi ? mymax : hi;
        }
    }
    reduce_and_publish(mymin, mymax, tid, lane, w);
}

// ---------------- Pass 1 generic (any n; scales only) ----------------
__global__ void __launch_bounds__(TPB)
pass1_generic(const float* __restrict__ x, int n, int nblocks) {
    const int tid  = threadIdx.x;
    const int lane = tid & 31;
    const int w    = tid >> 5;
    const int warp = (blockIdx.x * TPB + tid) >> 5;
    const int nw   = (gridDim.x * TPB) >> 5;
    unsigned mymin = 0xFFFFFFFFu, mymax = 0u;

    for (int b = warp; b < nblocks; b += nw) {
        long base = (long)b * QBLK + lane * 2;
        float x0 = 0.0f, x1 = 0.0f;
        if (base + 1 < (long)n) {
            float2 t = *reinterpret_cast<const float2*>(x + base);
            x0 = t.x; x1 = t.y;
        } else if (base < (long)n) {
            x0 = x[base];
        }
        unsigned b0 = absbits(x0), b1 = absbits(x1);
        unsigned w4 = 0u, w5 = 0u;
        #pragma unroll
        for (int r = 0; r < 5; ++r) {
            unsigned m  = max(b0, b1);
            unsigned ww = __reduce_max_sync(0xFFFFFFFFu, m);
            if (r == 3) w4 = ww;
            if (r == 4) w5 = ww;
            else {
                unsigned bal = __ballot_sync(0xFFFFFFFFu, m == ww);
                if (lane == __ffs((int)bal) - 1) { if (b0 == ww) b0 = 0u; else b1 = 0u; }
            }
        }
        if (lane == 0) {
            float s = fmaxf(fmaf(0.85f, __uint_as_float(w4) - __uint_as_float(w5),
                                 __uint_as_float(w5)), 1e-8f);
            g_scales[b] = s;
            unsigned sb = __float_as_uint(s);
            mymin = mymin < sb ? mymin : sb;
            mymax = mymax > sb ? mymax : sb;
        }
    }
    reduce_and_publish(mymin, mymax, tid, lane, w);
}

// ---------------- Pass 2 fast: decode codes ----------------
__global__ void __launch_bounds__(TPB)
pass2_fast(float* __restrict__ out, int nchunks) {
    const int gtid = blockIdx.x * TPB + threadIdx.x;
    const int NT   = gridDim.x * TPB;

    float4 gmm = g_gmm;
    const float smin = gmm.x, ssc = gmm.y, rss = gmm.z;
    float4* __restrict__ o4 = reinterpret_cast<float4*>(out);

    for (int c = gtid; c < nchunks; c += NT) {
        uint4 wv = g_codes4[c];
        float s  = g_scales[c >> 2];
        float q  = rintf((s - smin) * rss);
        q = fminf(fmaxf(q, 0.0f), 255.0f);
        float dqq = q * ssc * 0.25f;             // deq / 4 (codes are 4*level)
        float4 r0, r1, r2, r3;
        r0.x = dec8(wv.x, 0x8880u, dqq); r0.y = dec8(wv.x, 0x9991u, dqq);
        r0.z = dec8(wv.x, 0xAAA2u, dqq); r0.w = dec8(wv.x, 0xBBB3u, dqq);
        r1.x = dec8(wv.y, 0x8880u, dqq); r1.y = dec8(wv.y, 0x9991u, dqq);
        r1.z = dec8(wv.y, 0xAAA2u, dqq); r1.w = dec8(wv.y, 0xBBB3u, dqq);
        r2.x = dec8(wv.z, 0x8880u, dqq); r2.y = dec8(wv.z, 0x9991u, dqq);
        r2.z = dec8(wv.z, 0xAAA2u, dqq); r2.w = dec8(wv.z, 0xBBB3u, dqq);
        r3.x = dec8(wv.w, 0x8880u, dqq); r3.y = dec8(wv.w, 0x9991u, dqq);
        r3.z = dec8(wv.w, 0xAAA2u, dqq); r3.w = dec8(wv.w, 0xBBB3u, dqq);
        __stcs(o4 + c * 4 + 0, r0);
        __stcs(o4 + c * 4 + 1, r1);
        __stcs(o4 + c * 4 + 2, r2);
        __stcs(o4 + c * 4 + 3, r3);
    }
}

// ---------------- Pass 2 generic: re-read x ----------------
__global__ void __launch_bounds__(TPB)
pass2_generic(const float* __restrict__ x, float* __restrict__ out, int n) {
    const int gtid = blockIdx.x * TPB + threadIdx.x;
    const int NT   = gridDim.x * TPB;
    float4 gmm = g_gmm;
    const float smin = gmm.x, ssc = gmm.y, rss = gmm.z;

    for (int i = gtid; i < n; i += NT) {
        float s = g_scales[i >> 6];
        float q = rintf((s - smin) * rss);
        q = fminf(fmaxf(q, 0.0f), 255.0f);
        out[i] = qdq_one(x[i], 1.0f / s, q * ssc);
    }
}

extern "C" void kernel_launch(void* const* d_in, const int* in_sizes, int n_in,
                              void* d_out, int out_size) {
    const float* x = (const float*)d_in[0];
    float* out = (float*)d_out;
    int n = in_sizes[0];
    int fast = ((n & 127) == 0) && ((n >> 6) <= MAX_QBLOCKS);

    if (fast) {
        pass1_fast<<<GRID1, TPB>>>(x, n >> 7);
        pass2_fast<<<GRID1, TPB>>>(out, n >> 4);
    } else {
        int nblocks = (n + QBLK - 1) / QBLK;
        pass1_generic<<<GRID1, TPB>>>(x, n, nblocks);
        pass2_generic<<<GRID1, TPB>>>(x, out, n);
    }
}

// round 11
// speedup vs baseline: 1.4360x; 1.1580x over previous
#include <cuda_runtime.h>
#include <cstdint>

// FP4Quantizer, 2-node pipeline (no init kernel):
//   pass1 (grid 4096x256): ILP-4 — each warp processes 4 blocks/iteration,
//          all loads batched up front (MLP=4); exact 5-REDUX/4-ballot top-5
//          per block; fused quantize to int8 codes (4*level*sign) stored in
//          element order; fence-counter last-CTA publishes (smin, ss, rss).
//   pass2 (grid 4096x256): one quad per thread — LDG.32 codes + PRMT
//          sign-extend + I2F + FMUL -> coalesced STG.128. Never re-reads x.

#define QBLK 64
#define MAX_QBLOCKS (262144 + 8192)
#define GRID1 4096
#define TPB   256

__device__ float    g_scales[MAX_QBLOCKS];
__device__ unsigned g_codes[MAX_QBLOCKS * 16];   // int8 codes, element order
__device__ unsigned g_pmin[GRID1];
__device__ unsigned g_pmax[GRID1];
__device__ unsigned g_ctr = 0;                   // wraps to 0 every launch
__device__ float4   g_gmm;                       // (smin, ss, rss, -)

__device__ __forceinline__ unsigned absbits(float f) {
    return __float_as_uint(f) & 0x7FFFFFFFu;
}

// quantize one value -> int code = 4*level*sign in {0,±3,±4,±6,±8,±12}
// (levels {0,.75,1,1.5,2,3}): round |x/s| to 1 mantissa bit, clamp [0.75,3]
// in u32 domain, zero at/below 0.375 (argmin tie-to-lower), LUT exp->4*level.
__device__ __forceinline__ int qc(float val, float inv) {
    float xs = val * inv;
    unsigned ub = __float_as_uint(xs);
    unsigned uu = ub & 0x7FFFFFFFu;
    unsigned t  = (uu + 0x00200000u) & 0xFFC00000u;
    t = t < 0x40400000u ? t : 0x40400000u;
    t = t > 0x3F400000u ? t : 0x3F400000u;
    // t>>20 in {0x3F4,0x3F8,0x3FC,0x400,0x404} -> {3,4,6,8,12}
    int lvl4 = (int)((0xC8643u >> ((t >> 20) - 0x3F4u)) & 0xFu);
    lvl4 = (uu > 0x3EC00000u) ? lvl4 : 0;
    return (ub & 0x80000000u) ? -lvl4 : lvl4;
}

// decode: sign-extend byte (PRMT), int->float, scale by deq/4
__device__ __forceinline__ float dec8(unsigned wv, unsigned sel, float dqq) {
    int t;
    asm("prmt.b32 %0, %1, %1, %2;" : "=r"(t) : "r"(wv), "r"(sel));
    return (float)t * dqq;
}

// generic-path quantize-dequantize (fallback only)
__device__ __forceinline__ float qdq_one(float xv, float inv, float deq) {
    float xs = xv * inv;
    unsigned ub = __float_as_uint(xs);
    unsigned uu = ub & 0x7FFFFFFFu;
    unsigned t  = (uu + 0x00200000u) & 0xFFC00000u;
    t = t < 0x40400000u ? t : 0x40400000u;
    t = t > 0x3F400000u ? t : 0x3F400000u;
    float lvl = (uu > 0x3EC00000u) ? __uint_as_float(t) : 0.0f;
    float o = lvl * deq;
    return __uint_as_float(__float_as_uint(o) | (ub & 0x80000000u));
}

// CTA partial -> global publish -> last CTA computes (smin, ss, rss).
__device__ __forceinline__ void reduce_and_publish(unsigned mymin, unsigned mymax,
                                                   int tid, int lane, int w) {
    __shared__ unsigned s_rmin[TPB / 32], s_rmax[TPB / 32];
    __shared__ int s_last;
    mymin = __reduce_min_sync(0xFFFFFFFFu, mymin);
    mymax = __reduce_max_sync(0xFFFFFFFFu, mymax);
    if (lane == 0) { s_rmin[w] = mymin; s_rmax[w] = mymax; }
    __syncthreads();
    if (tid == 0) {
        unsigned a = 0xFFFFFFFFu, b = 0u;
        #pragma unroll
        for (int i = 0; i < TPB / 32; ++i) {
            a = a < s_rmin[i] ? a : s_rmin[i];
            b = b > s_rmax[i] ? b : s_rmax[i];
        }
        g_pmin[blockIdx.x] = a;
        g_pmax[blockIdx.x] = b;
        __threadfence();
        unsigned old = atomicInc(&g_ctr, gridDim.x - 1);  // wraps to 0 each launch
        s_last = (old == gridDim.x - 1);
    }
    __syncthreads();
    if (s_last) {
        unsigned lmin = 0xFFFFFFFFu, lmax = 0u;
        for (int i = tid; i < (int)gridDim.x; i += TPB) {
            unsigned a = __ldcg(&g_pmin[i]);
            unsigned b = __ldcg(&g_pmax[i]);
            lmin = lmin < a ? lmin : a;
            lmax = lmax > b ? lmax : b;
        }
        lmin = __reduce_min_sync(0xFFFFFFFFu, lmin);
        lmax = __reduce_max_sync(0xFFFFFFFFu, lmax);
        if (lane == 0) { s_rmin[w] = lmin; s_rmax[w] = lmax; }
        __syncthreads();
        if (tid == 0) {
            unsigned a = 0xFFFFFFFFu, b = 0u;
            #pragma unroll
            for (int i = 0; i < TPB / 32; ++i) {
                a = a < s_rmin[i] ? a : s_rmin[i];
                b = b > s_rmax[i] ? b : s_rmax[i];
            }
            float smin = __uint_as_float(a);
            float smax = __uint_as_float(b);
            bool  cond = smax > smin;
            float dd   = smax - smin;
            float ssc  = cond ? dd * (1.0f / 255.0f) : 1.0f;
            float rss  = cond ? 255.0f / dd : 0.0f;
            g_gmm = make_float4(smin, ssc, rss, 0.0f);
        }
    }
}

// ---------------- Pass 1 fast (n % 256 == 0) ----------------
// One warp handles 4 blocks per iteration. All 4 float2 loads issued before
// the chains (MLP=4). Exact top-5: 5 REDUX rounds, ballot-clear exactly one
// instance per round. REDUX results warp-uniform -> every lane quantizes its
// own 2 elems per block.
__global__ void __launch_bounds__(TPB)
pass1_fast(const float* __restrict__ x, int ngroups) {
    const int tid  = threadIdx.x;
    const int lane = tid & 31;
    const int w    = tid >> 5;
    const int warp = (blockIdx.x * TPB + tid) >> 5;
    const int nw   = (gridDim.x * TPB) >> 5;
    unsigned mymin = 0xFFFFFFFFu, mymax = 0u;
    short* codes16 = reinterpret_cast<short*>(g_codes);

    for (int g = warp; g < ngroups; g += nw) {
        const float2* __restrict__ x2 =
            reinterpret_cast<const float2*>(x + (long)g * 256);
        // batched loads: 4 x LDG.64, 1KB in flight per warp
        float2 v0 = x2[lane];
        float2 v1 = x2[32 + lane];
        float2 v2 = x2[64 + lane];
        float2 v3 = x2[96 + lane];

        unsigned A0 = absbits(v0.x), B0 = absbits(v0.y);
        unsigned A1 = absbits(v1.x), B1 = absbits(v1.y);
        unsigned A2 = absbits(v2.x), B2 = absbits(v2.y);
        unsigned A3 = absbits(v3.x), B3 = absbits(v3.y);

        unsigned w40, w41, w42, w43, w50, w51, w52, w53;
        #pragma unroll
        for (int r = 0; r < 5; ++r) {
            unsigned m0 = max(A0, B0), m1 = max(A1, B1);
            unsigned m2 = max(A2, B2), m3 = max(A3, B3);
            unsigned W0 = __reduce_max_sync(0xFFFFFFFFu, m0);
            unsigned W1 = __reduce_max_sync(0xFFFFFFFFu, m1);
            unsigned W2 = __reduce_max_sync(0xFFFFFFFFu, m2);
            unsigned W3 = __reduce_max_sync(0xFFFFFFFFu, m3);
            if (r == 3) { w40 = W0; w41 = W1; w42 = W2; w43 = W3; }
            if (r == 4) { w50 = W0; w51 = W1; w52 = W2; w53 = W3; }
            else {
                unsigned bl0 = __ballot_sync(0xFFFFFFFFu, m0 == W0);
                unsigned bl1 = __ballot_sync(0xFFFFFFFFu, m1 == W1);
                unsigned bl2 = __ballot_sync(0xFFFFFFFFu, m2 == W2);
                unsigned bl3 = __ballot_sync(0xFFFFFFFFu, m3 == W3);
                if (lane == __ffs((int)bl0) - 1) { if (A0 == W0) A0 = 0u; else B0 = 0u; }
                if (lane == __ffs((int)bl1) - 1) { if (A1 == W1) A1 = 0u; else B1 = 0u; }
                if (lane == __ffs((int)bl2) - 1) { if (A2 == W2) A2 = 0u; else B2 = 0u; }
                if (lane == __ffs((int)bl3) - 1) { if (A3 == W3) A3 = 0u; else B3 = 0u; }
            }
        }
        // warp-uniform scales
        float s0 = fmaxf(fmaf(0.85f, __uint_as_float(w40) - __uint_as_float(w50),
                              __uint_as_float(w50)), 1e-8f);
        float s1 = fmaxf(fmaf(0.85f, __uint_as_float(w41) - __uint_as_float(w51),
                              __uint_as_float(w51)), 1e-8f);
        float s2 = fmaxf(fmaf(0.85f, __uint_as_float(w42) - __uint_as_float(w52),
                              __uint_as_float(w52)), 1e-8f);
        float s3 = fmaxf(fmaf(0.85f, __uint_as_float(w43) - __uint_as_float(w53),
                              __uint_as_float(w53)), 1e-8f);
        float i0 = 1.0f / s0, i1 = 1.0f / s1, i2 = 1.0f / s2, i3 = 1.0f / s3;

        int blk = 4 * g;
        int c0a = qc(v0.x, i0), c0b = qc(v0.y, i0);
        int c1a = qc(v1.x, i1), c1b = qc(v1.y, i1);
        int c2a = qc(v2.x, i2), c2b = qc(v2.y, i2);
        int c3a = qc(v3.x, i3), c3b = qc(v3.y, i3);
        codes16[(blk + 0) * 32 + lane] = (short)((c0a & 0xFF) | ((c0b & 0xFF) << 8));
        codes16[(blk + 1) * 32 + lane] = (short)((c1a & 0xFF) | ((c1b & 0xFF) << 8));
        codes16[(blk + 2) * 32 + lane] = (short)((c2a & 0xFF) | ((c2b & 0xFF) << 8));
        codes16[(blk + 3) * 32 + lane] = (short)((c3a & 0xFF) | ((c3b & 0xFF) << 8));

        if (lane == 0) {
            *reinterpret_cast<float4*>(&g_scales[blk]) = make_float4(s0, s1, s2, s3);
            unsigned u0 = __float_as_uint(s0), u1 = __float_as_uint(s1);
            unsigned u2 = __float_as_uint(s2), u3 = __float_as_uint(s3);
            unsigned lo = min(min(u0, u1), min(u2, u3));
            unsigned hi = max(max(u0, u1), max(u2, u3));
            mymin = mymin < lo ? mymin : lo;
            mymax = mymax > hi ? mymax : hi;
        }
    }
    reduce_and_publish(mymin, mymax, tid, lane, w);
}

// ---------------- Pass 1 generic (any n; scales only) ----------------
__global__ void __launch_bounds__(TPB)
pass1_generic(const float* __restrict__ x, int n, int nblocks) {
    const int tid  = threadIdx.x;
    const int lane = tid & 31;
    const int w    = tid >> 5;
    const int warp = (blockIdx.x * TPB + tid) >> 5;
    const int nw   = (gridDim.x * TPB) >> 5;
    unsigned mymin = 0xFFFFFFFFu, mymax = 0u;

    for (int b = warp; b < nblocks; b += nw) {
        long base = (long)b * QBLK + lane * 2;
        float x0 = 0.0f, x1 = 0.0f;
        if (base + 1 < (long)n) {
            float2 t = *reinterpret_cast<const float2*>(x + base);
            x0 = t.x; x1 = t.y;
        } else if (base < (long)n) {
            x0 = x[base];
        }
        unsigned b0 = absbits(x0), b1 = absbits(x1);
        unsigned w4 = 0u, w5 = 0u;
        #pragma unroll
        for (int r = 0; r < 5; ++r) {
            unsigned m  = max(b0, b1);
            unsigned ww = __reduce_max_sync(0xFFFFFFFFu, m);
            if (r == 3) w4 = ww;
            if (r == 4) w5 = ww;
            else {
                unsigned bal = __ballot_sync(0xFFFFFFFFu, m == ww);
                if (lane == __ffs((int)bal) - 1) { if (b0 == ww) b0 = 0u; else b1 = 0u; }
            }
        }
        if (lane == 0) {
            float s = fmaxf(fmaf(0.85f, __uint_as_float(w4) - __uint_as_float(w5),
                                 __uint_as_float(w5)), 1e-8f);
            g_scales[b] = s;
            unsigned sb = __float_as_uint(s);
            mymin = mymin < sb ? mymin : sb;
            mymax = mymax > sb ? mymax : sb;
        }
    }
    reduce_and_publish(mymin, mymax, tid, lane, w);
}

// ---------------- Pass 2 fast: decode codes, quad per thread ----------------
__global__ void __launch_bounds__(TPB)
pass2_fast(float* __restrict__ out, int nquads) {
    const int gtid = blockIdx.x * TPB + threadIdx.x;
    const int NT   = gridDim.x * TPB;

    float4 gmm = g_gmm;
    const float smin = gmm.x, ssc = gmm.y, rss = gmm.z;
    float4* __restrict__ o4 = reinterpret_cast<float4*>(out);

    for (int q = gtid; q < nquads; q += NT) {
        unsigned cw = g_codes[q];                // 4 int8 codes
        float s  = g_scales[q >> 4];
        float qq = rintf((s - smin) * rss);
        qq = fminf(fmaxf(qq, 0.0f), 255.0f);
        float dqq = qq * ssc * 0.25f;            // deq / 4 (codes are 4*level)
        float4 r;
        r.x = dec8(cw, 0x8880u, dqq);
        r.y = dec8(cw, 0x9991u, dqq);
        r.z = dec8(cw, 0xAAA2u, dqq);
        r.w = dec8(cw, 0xBBB3u, dqq);
        __stcs(o4 + q, r);
    }
}

// ---------------- Pass 2 generic: re-read x ----------------
__global__ void __launch_bounds__(TPB)
pass2_generic(const float* __restrict__ x, float* __restrict__ out, int n) {
    const int gtid = blockIdx.x * TPB + threadIdx.x;
    const int NT   = gridDim.x * TPB;
    float4 gmm = g_gmm;
    const float smin = gmm.x, ssc = gmm.y, rss = gmm.z;

    for (int i = gtid; i < n; i += NT) {
        float s = g_scales[i >> 6];
        float q = rintf((s - smin) * rss);
        q = fminf(fmaxf(q, 0.0f), 255.0f);
        out[i] = qdq_one(x[i], 1.0f / s, q * ssc);
    }
}

extern "C" void kernel_launch(void* const* d_in, const int* in_sizes, int n_in,
                              void* d_out, int out_size) {
    const float* x = (const float*)d_in[0];
    float* out = (float*)d_out;
    int n = in_sizes[0];
    int fast = ((n & 255) == 0) && ((n >> 6) <= MAX_QBLOCKS);

    if (fast) {
        pass1_fast<<<GRID1, TPB>>>(x, n >> 8);
        pass2_fast<<<GRID1, TPB>>>(out, n >> 2);
    } else {
        int nblocks = (n + QBLK - 1) / QBLK;
        pass1_generic<<<GRID1, TPB>>>(x, n, nblocks);
        pass2_generic<<<GRID1, TPB>>>(x, out, n);
    }
}

// round 12
// speedup vs baseline: 1.6709x; 1.1635x over previous
#include <cuda_runtime.h>
#include <cstdint>

// FP4Quantizer, 2-node pipeline (no init kernel):
//   pass1 (grid 4096x256): scales ONLY. ILP-4 — each warp processes 4
//          blocks/iteration, 4 float2 loads batched up front (1KB in
//          flight); exact 5-REDUX/4-ballot top-5 per block; lane0 stores
//          (1/s, s) per block; fence-counter last-CTA publishes
//          (smin, ss, rss) to g_gmm.
//   pass2 (grid 4096x256): re-reads x (L2-resident after pass1), one quad
//          per thread, inline deq(s), branchless bit-trick quantize-
//          dequantize, streaming stores.

#define QBLK 64
#define MAX_QBLOCKS (262144 + 8192)
#define GRID1 4096
#define TPB   256

__device__ float2   g_bs[MAX_QBLOCKS];   // (inv_scale, scale)
__device__ unsigned g_pmin[GRID1];
__device__ unsigned g_pmax[GRID1];
__device__ unsigned g_ctr = 0;           // wraps to 0 every launch
__device__ float4   g_gmm;               // (smin, ss, rss, -)

__device__ __forceinline__ unsigned absbits(float f) {
    return __float_as_uint(f) & 0x7FFFFFFFu;
}

// CTA partial -> global publish -> last CTA computes (smin, ss, rss).
__device__ __forceinline__ void reduce_and_publish(unsigned mymin, unsigned mymax,
                                                   int tid, int lane, int w) {
    __shared__ unsigned s_rmin[TPB / 32], s_rmax[TPB / 32];
    __shared__ int s_last;
    mymin = __reduce_min_sync(0xFFFFFFFFu, mymin);
    mymax = __reduce_max_sync(0xFFFFFFFFu, mymax);
    if (lane == 0) { s_rmin[w] = mymin; s_rmax[w] = mymax; }
    __syncthreads();
    if (tid == 0) {
        unsigned a = 0xFFFFFFFFu, b = 0u;
        #pragma unroll
        for (int i = 0; i < TPB / 32; ++i) {
            a = a < s_rmin[i] ? a : s_rmin[i];
            b = b > s_rmax[i] ? b : s_rmax[i];
        }
        g_pmin[blockIdx.x] = a;
        g_pmax[blockIdx.x] = b;
        __threadfence();
        unsigned old = atomicInc(&g_ctr, gridDim.x - 1);  // wraps to 0 each launch
        s_last = (old == gridDim.x - 1);
    }
    __syncthreads();
    if (s_last) {
        unsigned lmin = 0xFFFFFFFFu, lmax = 0u;
        for (int i = tid; i < (int)gridDim.x; i += TPB) {
            unsigned a = __ldcg(&g_pmin[i]);
            unsigned b = __ldcg(&g_pmax[i]);
            lmin = lmin < a ? lmin : a;
            lmax = lmax > b ? lmax : b;
        }
        lmin = __reduce_min_sync(0xFFFFFFFFu, lmin);
        lmax = __reduce_max_sync(0xFFFFFFFFu, lmax);
        if (lane == 0) { s_rmin[w] = lmin; s_rmax[w] = lmax; }
        __syncthreads();
        if (tid == 0) {
            unsigned a = 0xFFFFFFFFu, b = 0u;
            #pragma unroll
            for (int i = 0; i < TPB / 32; ++i) {
                a = a < s_rmin[i] ? a : s_rmin[i];
                b = b > s_rmax[i] ? b : s_rmax[i];
            }
            float smin = __uint_as_float(a);
            float smax = __uint_as_float(b);
            bool  cond = smax > smin;
            float dd   = smax - smin;
            float ssc  = cond ? dd * (1.0f / 255.0f) : 1.0f;
            float rss  = cond ? 255.0f / dd : 0.0f;
            g_gmm = make_float4(smin, ssc, rss, 0.0f);
        }
    }
}

// ---------------- Pass 1 fast (n % 256 == 0) ----------------
// One warp handles 4 blocks per iteration; all 4 loads issued up front.
// Exact top-5 per block: 5 REDUX rounds, ballot-clear exactly ONE instance
// per round. Rounds 3/4 give the 4th/5th largest |x| (sorted[60]/sorted[59]);
// quantile(0.95, 64) = s59 + 0.85*(s60 - s59).
__global__ void __launch_bounds__(TPB)
pass1_fast(const float* __restrict__ x, int ngroups) {
    const int tid  = threadIdx.x;
    const int lane = tid & 31;
    const int w    = tid >> 5;
    const int warp = (blockIdx.x * TPB + tid) >> 5;
    const int nw   = (gridDim.x * TPB) >> 5;
    unsigned mymin = 0xFFFFFFFFu, mymax = 0u;

    for (int g = warp; g < ngroups; g += nw) {
        const float2* __restrict__ x2 =
            reinterpret_cast<const float2*>(x + (long)g * 256);
        float2 v0 = x2[lane];
        float2 v1 = x2[32 + lane];
        float2 v2 = x2[64 + lane];
        float2 v3 = x2[96 + lane];

        unsigned A0 = absbits(v0.x), B0 = absbits(v0.y);
        unsigned A1 = absbits(v1.x), B1 = absbits(v1.y);
        unsigned A2 = absbits(v2.x), B2 = absbits(v2.y);
        unsigned A3 = absbits(v3.x), B3 = absbits(v3.y);

        unsigned w40, w41, w42, w43, w50, w51, w52, w53;
        #pragma unroll
        for (int r = 0; r < 5; ++r) {
            unsigned m0 = max(A0, B0), m1 = max(A1, B1);
            unsigned m2 = max(A2, B2), m3 = max(A3, B3);
            unsigned W0 = __reduce_max_sync(0xFFFFFFFFu, m0);
            unsigned W1 = __reduce_max_sync(0xFFFFFFFFu, m1);
            unsigned W2 = __reduce_max_sync(0xFFFFFFFFu, m2);
            unsigned W3 = __reduce_max_sync(0xFFFFFFFFu, m3);
            if (r == 3) { w40 = W0; w41 = W1; w42 = W2; w43 = W3; }
            if (r == 4) { w50 = W0; w51 = W1; w52 = W2; w53 = W3; }
            else {
                unsigned bl0 = __ballot_sync(0xFFFFFFFFu, m0 == W0);
                unsigned bl1 = __ballot_sync(0xFFFFFFFFu, m1 == W1);
                unsigned bl2 = __ballot_sync(0xFFFFFFFFu, m2 == W2);
                unsigned bl3 = __ballot_sync(0xFFFFFFFFu, m3 == W3);
                if (lane == __ffs((int)bl0) - 1) { if (A0 == W0) A0 = 0u; else B0 = 0u; }
                if (lane == __ffs((int)bl1) - 1) { if (A1 == W1) A1 = 0u; else B1 = 0u; }
                if (lane == __ffs((int)bl2) - 1) { if (A2 == W2) A2 = 0u; else B2 = 0u; }
                if (lane == __ffs((int)bl3) - 1) { if (A3 == W3) A3 = 0u; else B3 = 0u; }
            }
        }
        if (lane == 0) {
            float s0 = fmaxf(fmaf(0.85f, __uint_as_float(w40) - __uint_as_float(w50),
                                  __uint_as_float(w50)), 1e-8f);
            float s1 = fmaxf(fmaf(0.85f, __uint_as_float(w41) - __uint_as_float(w51),
                                  __uint_as_float(w51)), 1e-8f);
            float s2 = fmaxf(fmaf(0.85f, __uint_as_float(w42) - __uint_as_float(w52),
                                  __uint_as_float(w52)), 1e-8f);
            float s3 = fmaxf(fmaf(0.85f, __uint_as_float(w43) - __uint_as_float(w53),
                                  __uint_as_float(w53)), 1e-8f);
            int blk = 4 * g;
            float4* bs4 = reinterpret_cast<float4*>(&g_bs[blk]);
            bs4[0] = make_float4(1.0f / s0, s0, 1.0f / s1, s1);
            bs4[1] = make_float4(1.0f / s2, s2, 1.0f / s3, s3);
            unsigned u0 = __float_as_uint(s0), u1 = __float_as_uint(s1);
            unsigned u2 = __float_as_uint(s2), u3 = __float_as_uint(s3);
            unsigned lo = min(min(u0, u1), min(u2, u3));
            unsigned hi = max(max(u0, u1), max(u2, u3));
            mymin = mymin < lo ? mymin : lo;
            mymax = mymax > hi ? mymax : hi;
        }
    }
    reduce_and_publish(mymin, mymax, tid, lane, w);
}

// ---------------- Pass 1 generic (any n) ----------------
__global__ void __launch_bounds__(TPB)
pass1_generic(const float* __restrict__ x, int n, int nblocks) {
    const int tid  = threadIdx.x;
    const int lane = tid & 31;
    const int w    = tid >> 5;
    const int warp = (blockIdx.x * TPB + tid) >> 5;
    const int nw   = (gridDim.x * TPB) >> 5;
    unsigned mymin = 0xFFFFFFFFu, mymax = 0u;

    for (int b = warp; b < nblocks; b += nw) {
        long base = (long)b * QBLK + lane * 2;
        float x0 = 0.0f, x1 = 0.0f;
        if (base + 1 < (long)n) {
            float2 t = *reinterpret_cast<const float2*>(x + base);
            x0 = t.x; x1 = t.y;
        } else if (base < (long)n) {
            x0 = x[base];
        }
        unsigned b0 = absbits(x0), b1 = absbits(x1);
        unsigned w4 = 0u, w5 = 0u;
        #pragma unroll
        for (int r = 0; r < 5; ++r) {
            unsigned m  = max(b0, b1);
            unsigned ww = __reduce_max_sync(0xFFFFFFFFu, m);
            if (r == 3) w4 = ww;
            if (r == 4) w5 = ww;
            else {
                unsigned bal = __ballot_sync(0xFFFFFFFFu, m == ww);
                if (lane == __ffs((int)bal) - 1) { if (b0 == ww) b0 = 0u; else b1 = 0u; }
            }
        }
        if (lane == 0) {
            float s = fmaxf(fmaf(0.85f, __uint_as_float(w4) - __uint_as_float(w5),
                                 __uint_as_float(w5)), 1e-8f);
            g_bs[b] = make_float2(1.0f / s, s);
            unsigned sb = __float_as_uint(s);
            mymin = mymin < sb ? mymin : sb;
            mymax = mymax > sb ? mymax : sb;
        }
    }
    reduce_and_publish(mymin, mymax, tid, lane, w);
}

// ---------------- Pass 2 ----------------
// Branchless nearest-level for {0, ±0.75, ±1, ±1.5, ±2, ±3}: round |x/s| to
// 1 mantissa bit, clamp [0.75, 3.0] as u32, zero at/below 0.375 (argmin
// tie-to-lower), multiply by deq, restore sign.
__device__ __forceinline__ float qdq_one(float xv, float inv, float deq) {
    float xs = xv * inv;
    unsigned ub = __float_as_uint(xs);
    unsigned uu = ub & 0x7FFFFFFFu;
    unsigned t  = (uu + 0x00200000u) & 0xFFC00000u;
    t = t < 0x40400000u ? t : 0x40400000u;
    t = t > 0x3F400000u ? t : 0x3F400000u;
    float lvl = (uu > 0x3EC00000u) ? __uint_as_float(t) : 0.0f;
    float o = lvl * deq;
    return __uint_as_float(__float_as_uint(o) | (ub & 0x80000000u));
}

// deq(s): double-quantized scale; rss==0 (degenerate) gives q=0 -> deq=0.
__device__ __forceinline__ float deq_of(float s, float smin, float rss, float ss) {
    float q = rintf((s - smin) * rss);
    q = fminf(fmaxf(q, 0.0f), 255.0f);
    return q * ss;
}

__global__ void __launch_bounds__(TPB)
pass2_kernel(const float* __restrict__ x, float* __restrict__ out, int n) {
    const int gtid = blockIdx.x * TPB + threadIdx.x;
    const int NT   = gridDim.x * TPB;
    const int nquads = n >> 2;

    float4 gmm = g_gmm;
    const float smin = gmm.x, ssc = gmm.y, rss = gmm.z;

    const float4* __restrict__ x4 = reinterpret_cast<const float4*>(x);
    float4* __restrict__ o4 = reinterpret_cast<float4*>(out);

    for (int q = gtid; q < nquads; q += NT) {
        float2 b = g_bs[q >> 4];
        float4 v = x4[q];
        float dq = deq_of(b.y, smin, rss, ssc);
        float4 r;
        r.x = qdq_one(v.x, b.x, dq);
        r.y = qdq_one(v.y, b.x, dq);
        r.z = qdq_one(v.z, b.x, dq);
        r.w = qdq_one(v.w, b.x, dq);
        __stcs(o4 + q, r);
    }
    // scalar tail (n not multiple of 4)
    for (int i = (nquads << 2) + gtid; i < n; i += NT) {
        float2 b = g_bs[i >> 6];
        float dq = deq_of(b.y, smin, rss, ssc);
        out[i] = qdq_one(x[i], b.x, dq);
    }
}

extern "C" void kernel_launch(void* const* d_in, const int* in_sizes, int n_in,
                              void* d_out, int out_size) {
    const float* x = (const float*)d_in[0];
    float* out = (float*)d_out;
    int n = in_sizes[0];

    if (((n & 255) == 0) && ((n >> 6) <= MAX_QBLOCKS)) {
        pass1_fast<<<GRID1, TPB>>>(x, n >> 8);
    } else {
        int nblocks = (n + QBLK - 1) / QBLK;
        pass1_generic<<<GRID1, TPB>>>(x, n, nblocks);
    }
    pass2_kernel<<<GRID1, TPB>>>(x, out, n);
}